// round 9
// baseline (speedup 1.0000x reference)
#include <cuda_runtime.h>
#include <cuda_fp16.h>
#include <cstdint>
#include <math.h>

#define N_ITEMS 8192
#define DIM     64
#define BATCHSZ 4096
#define LN2F    0.69314718055994531f
#define INV_T   14.285714285714286f
#define ITLG2E  20.609947181438156f   /* (1/0.07) * log2(e) */
#define NTILES  2080                  /* 64*65/2 upper-triangle 128x128 tiles */
#define GRID_SY 148

// ---------------- device scratch (no allocations allowed) ----------------
__device__ uint32_t g_fh[N_ITEMS * 32];   // normalized rows, half2-packed [row][32]
__device__ float    g_Z[N_ITEMS];         // exp-sums (atomic accumulated)
__device__ float    g_S[56 * 64];         // per-class feature sums
__device__ int      g_N[56];              // per-class counts

// ---------------- helpers --------------------------------------------------
static __device__ __forceinline__ uint32_t smem_u32(const void* p) {
    uint32_t a;
    asm("{ .reg .u64 t; cvta.to.shared.u64 t, %1; cvt.u32.u64 %0, t; }" : "=r"(a) : "l"(p));
    return a;
}
static __device__ __forceinline__ float ex2f(float x) {
    float y; asm("ex2.approx.ftz.f32 %0, %1;" : "=f"(y) : "f"(x)); return y;
}
static __device__ __forceinline__ float lg2f(float x) {
    float y; asm("lg2.approx.ftz.f32 %0, %1;" : "=f"(y) : "f"(x)); return y;
}
static __device__ __forceinline__ void cp16(uint32_t dst, const void* src) {
    asm volatile("cp.async.cg.shared.global [%0], [%1], 16;" :: "r"(dst), "l"(src));
}
#define CP_COMMIT() asm volatile("cp.async.commit_group;" ::: "memory")
static __device__ __forceinline__ void ldsm4(uint32_t* r, uint32_t addr) {
    asm volatile("ldmatrix.sync.aligned.m8n8.x4.shared.b16 {%0,%1,%2,%3}, [%4];"
                 : "=r"(r[0]), "=r"(r[1]), "=r"(r[2]), "=r"(r[3]) : "r"(addr));
}
static __device__ __forceinline__ void mma16816(float* d, const uint32_t* a,
                                                uint32_t b0, uint32_t b1) {
    asm volatile("mma.sync.aligned.m16n8k16.row.col.f32.f16.f16.f32 "
                 "{%0,%1,%2,%3}, {%4,%5,%6,%7}, {%8,%9}, {%0,%1,%2,%3};"
                 : "+f"(d[0]), "+f"(d[1]), "+f"(d[2]), "+f"(d[3])
                 : "r"(a[0]), "r"(a[1]), "r"(a[2]), "r"(a[3]), "r"(b0), "r"(b1));
}

// ---------------- kernel 1: normalize + rating + zero scratch --------------
__global__ __launch_bounds__(256) void prep_kernel(const float* __restrict__ emb,
                                                   const int* __restrict__ idx,
                                                   const float* __restrict__ w,
                                                   const float* __restrict__ bias,
                                                   float* __restrict__ out) {
    int bid  = blockIdx.x;
    int wid  = threadIdx.x >> 5;
    int lane = threadIdx.x & 31;
    if (bid < N_ITEMS / 8) {
        int row = bid * 8 + wid;
        float2 v = reinterpret_cast<const float2*>(emb + (size_t)row * DIM)[lane];
        float ss = v.x * v.x + v.y * v.y;
        #pragma unroll
        for (int o = 16; o; o >>= 1) ss += __shfl_xor_sync(0xFFFFFFFFu, ss, o);
        float inv = 1.0f / fmaxf(sqrtf(ss), 1e-12f);
        __half2 h = __floats2half2_rn(v.x * inv, v.y * inv);
        g_fh[row * 32 + lane] = *reinterpret_cast<uint32_t*>(&h);
    } else if (bid < N_ITEMS / 8 + BATCHSZ / 8) {
        int r = (bid - N_ITEMS / 8) * 8 + wid;
        int it = idx[r];
        float2 v  = reinterpret_cast<const float2*>(emb + (size_t)it * DIM)[lane];
        float2 ww = reinterpret_cast<const float2*>(w)[lane];
        float s = v.x * ww.x + v.y * ww.y;
        #pragma unroll
        for (int o = 16; o; o >>= 1) s += __shfl_xor_sync(0xFFFFFFFFu, s, o);
        if (lane == 0) out[r] = 1.0f / (1.0f + __expf(-(s + bias[0])));
    } else {
        int flat = (bid - 1536) * 1024 + threadIdx.x * 4;
        #pragma unroll
        for (int k = 0; k < 4; k++) {
            int f = flat + k;
            if (f < N_ITEMS) g_Z[f] = 0.f;
            else if (f < N_ITEMS + 3584) g_S[f - N_ITEMS] = 0.f;
            else if (f < N_ITEMS + 3584 + 56) g_N[f - N_ITEMS - 3584] = 0;
        }
    }
}

// ---------------- kernel 2: per-class feature sums -------------------------
// grid 64 x 512 thr. CTA b: rows b*128..+127. Thread: dim d=tid&63,
// class group g=tid>>6 handles classes [g*7, g*7+7).
__global__ __launch_bounds__(512) void classsum_kernel(const int* __restrict__ labels) {
    __shared__ int sl[128];
    int tid = threadIdx.x;
    int d = tid & 63, g = tid >> 6, c0 = g * 7;
    if (tid < 128) sl[tid] = labels[blockIdx.x * 128 + tid];
    __syncthreads();
    float a[7] = {0, 0, 0, 0, 0, 0, 0};
    int   n[7] = {0, 0, 0, 0, 0, 0, 0};
    for (int r = 0; r < 128; r++) {
        int rel = sl[r] - c0;
        if ((unsigned)rel < 7u) {
            uint32_t p = g_fh[(size_t)(blockIdx.x * 128 + r) * 32 + (d >> 1)];
            __half2 h = *reinterpret_cast<__half2*>(&p);
            float v = (d & 1) ? __high2float(h) : __low2float(h);
            #pragma unroll
            for (int q = 0; q < 7; q++) if (rel == q) { a[q] += v; n[q]++; }
        }
    }
    #pragma unroll
    for (int q = 0; q < 7; q++) {
        atomicAdd(&g_S[(c0 + q) * 64 + d], a[q]);
        if (d == 0) atomicAdd(&g_N[c0 + q], n[q]);
    }
}

// ---------------- kernel 3: symmetric Z-only GEMM --------------------------
// 148 persistent CTAs x 512 thr. Tiles w = bid + 148*s over upper triangle.
// Tile (ti,tj): rows band ti, cols band tj. Row sums -> g_Z[ti band];
// if ti<tj also col sums -> g_Z[tj band] (e_ij == e_ji).
// smem: ring 2 x {A 16K, B 16K} = 64K; stage_col [16][64]f; stage_row [2][128]f.
static __device__ __forceinline__ void decode_tile(int w, int& ti, int& tj) {
    float disc = 16641.0f - 8.0f * (float)w;
    int t = (int)((129.0f - sqrtf(disc)) * 0.5f);
    if (t > 63) t = 63;
    if (t < 0) t = 0;
    while (t > 0 && (t * (129 - t)) / 2 > w) t--;
    while (t < 63 && ((t + 1) * (128 - t)) / 2 <= w) t++;
    ti = t;
    tj = t + (w - (t * (129 - t)) / 2);
}
static __device__ __forceinline__ void load_band(uint32_t sdst, int band, int tid) {
    const char* gsrc = (const char*)g_fh + (size_t)band * 16384;
    #pragma unroll
    for (int i = tid; i < 1024; i += 512) {
        uint32_t off = ((i >> 3) * 128) + ((i & 7) * 16);
        uint32_t sw  = off ^ ((off >> 3) & 0x70);
        cp16(sdst + sw, gsrc + off);
    }
}

__global__ __launch_bounds__(512, 1) void supcon_kernel() {
    extern __shared__ char dyn[];
    float* stage_col = reinterpret_cast<float*>(dyn + 65536);   // [16][64]
    float* stage_row = stage_col + 16 * 64;                     // [2][128]

    const int tid  = threadIdx.x;
    const int w    = tid >> 5;
    const int lane = tid & 31;
    const int wr   = w & 7;
    const int wc   = w >> 3;
    const uint32_t sbase = smem_u32(dyn);
    const int bnoff = (((lane >> 4) & 1) << 3) + (lane & 7);
    const uint32_t bksel = (uint32_t)((lane >> 3) & 1);
    const float negM = -ITLG2E;

    int ti, tj;
    decode_tile(blockIdx.x, ti, tj);
    load_band(sbase, ti, tid);
    load_band(sbase + 16384, tj, tid);
    CP_COMMIT();

    int st = 0;
    for (int wjob = blockIdx.x; wjob < NTILES; wjob += GRID_SY) {
        int tin = ti, tjn = tj;
        int wn = wjob + GRID_SY;
        if (wn < NTILES) decode_tile(wn, tin, tjn);
        uint32_t nstage = sbase + (uint32_t)(st ^ 1) * 32768;
        load_band(nstage, tin, tid);
        load_band(nstage + 16384, tjn, tid);
        CP_COMMIT();
        asm volatile("cp.async.wait_group 1;" ::: "memory");
        __syncthreads();                      // current tile resident

        const uint32_t Ab = sbase + (uint32_t)st * 32768;
        const uint32_t Bb = Ab + 16384;

        uint32_t ah[4][4];
        {
            int arow = wr * 16 + (lane & 15);
            uint32_t rbase = Ab + (uint32_t)arow * 128;
            #pragma unroll
            for (int ks = 0; ks < 4; ks++) {
                uint32_t c = (uint32_t)(ks * 2 + (lane >> 4));
                ldsm4(ah[ks], rbase + ((c ^ (arow & 7)) << 4));
            }
        }

        float rowZ0 = 0.f, rowZ1 = 0.f;
        #pragma unroll
        for (int ntp = 0; ntp < 4; ntp++) {
            float a0[4] = {0.f, 0.f, 0.f, 0.f};
            float a1[4] = {0.f, 0.f, 0.f, 0.f};
            int n = wc * 64 + ntp * 16 + bnoff;
            uint32_t nb = Bb + (uint32_t)n * 128;
            #pragma unroll
            for (int ks = 0; ks < 4; ks++) {
                uint32_t c = (uint32_t)(ks * 2) + bksel;
                uint32_t bb[4];
                ldsm4(bb, nb + ((c ^ (n & 7)) << 4));
                mma16816(a0, ah[ks], bb[0], bb[1]);
                mma16816(a1, ah[ks], bb[2], bb[3]);
            }
            float e00 = ex2f(fmaf(a0[0], ITLG2E, negM));
            float e01 = ex2f(fmaf(a0[1], ITLG2E, negM));
            float e10 = ex2f(fmaf(a0[2], ITLG2E, negM));
            float e11 = ex2f(fmaf(a0[3], ITLG2E, negM));
            float f00 = ex2f(fmaf(a1[0], ITLG2E, negM));
            float f01 = ex2f(fmaf(a1[1], ITLG2E, negM));
            float f10 = ex2f(fmaf(a1[2], ITLG2E, negM));
            float f11 = ex2f(fmaf(a1[3], ITLG2E, negM));
            rowZ0 += (e00 + e01) + (f00 + f01);
            rowZ1 += (e10 + e11) + (f10 + f11);
            // column sums across the 16 rows of this warp
            float cz0 = e00 + e10, cz1 = e01 + e11;
            float cz2 = f00 + f10, cz3 = f01 + f11;
            #pragma unroll
            for (int off = 4; off <= 16; off <<= 1) {
                cz0 += __shfl_xor_sync(0xFFFFFFFFu, cz0, off);
                cz1 += __shfl_xor_sync(0xFFFFFFFFu, cz1, off);
                cz2 += __shfl_xor_sync(0xFFFFFFFFu, cz2, off);
                cz3 += __shfl_xor_sync(0xFFFFFFFFu, cz3, off);
            }
            if (lane < 4) {
                int cl = ntp * 16 + 2 * lane;
                stage_col[w * 64 + cl]     = cz0;
                stage_col[w * 64 + cl + 1] = cz1;
                stage_col[w * 64 + cl + 8] = cz2;
                stage_col[w * 64 + cl + 9] = cz3;
            }
        }
        #pragma unroll
        for (int off = 1; off <= 2; off <<= 1) {
            rowZ0 += __shfl_xor_sync(0xFFFFFFFFu, rowZ0, off);
            rowZ1 += __shfl_xor_sync(0xFFFFFFFFu, rowZ1, off);
        }
        if ((lane & 3) == 0) {
            int r0 = wr * 16 + (lane >> 2);
            stage_row[wc * 128 + r0]     = rowZ0;
            stage_row[wc * 128 + r0 + 8] = rowZ1;
        }
        __syncthreads();                      // stages complete
        if (tid < 128) {
            if (ti != tj) {
                int whalf = (tid >> 6) * 8;   // cols 0-63 <- warps wc=0; 64-127 <- wc=1
                int cl = tid & 63;
                float v = 0.f;
                #pragma unroll
                for (int k = 0; k < 8; k++) v += stage_col[(whalf + k) * 64 + cl];
                atomicAdd(&g_Z[tj * 128 + tid], v);
            }
        } else if (tid < 256) {
            int r = tid - 128;
            atomicAdd(&g_Z[ti * 128 + r], stage_row[r] + stage_row[128 + r]);
        }
        ti = tin; tj = tjn; st ^= 1;
    }
}

// ---------------- kernel 4: finalize loss ----------------------------------
__global__ __launch_bounds__(1024) void finalize_kernel(const int* __restrict__ labels,
                                                        float* __restrict__ out,
                                                        int out_size) {
    __shared__ float Ss[3584];
    __shared__ float ns[56];
    __shared__ float red[1024];
    int tid = threadIdx.x;
    for (int i = tid; i < 3584; i += 1024) Ss[i] = g_S[i];
    if (tid < 56) ns[tid] = (float)g_N[tid];
    __syncthreads();

    float acc = 0.f;
    #pragma unroll
    for (int k = 0; k < 8; k++) {
        int r = tid + k * 1024;
        int lab = labels[r];
        const float* Sl = &Ss[lab * 64];
        float sii = 0.f, di = 0.f;
        #pragma unroll
        for (int j = 0; j < 32; j++) {
            uint32_t p = g_fh[(size_t)r * 32 + j];
            __half2 h = *reinterpret_cast<__half2*>(&p);
            float f0 = __low2float(h), f1 = __high2float(h);
            sii = fmaf(f0, f0, fmaf(f1, f1, sii));
            di  = fmaf(f0, Sl[2 * j], fmaf(f1, Sl[2 * j + 1], di));
        }
        float Cc  = ns[lab] - 1.0f;
        float eD  = ex2f((sii - 1.0f) * ITLG2E);      // diagonal exp term
        float Zv  = g_Z[r] - eD;                      // exclude self
        float Pln = (di - sii - Cc) * INV_T;          // sum of positive logits (ln)
        float lnZ = lg2f(Zv + 1e-6f) * LN2F;
        acc += (Pln - Cc * lnZ) / (Cc + 1e-6f);
    }
    red[tid] = acc;
    __syncthreads();
    for (int o = 512; o; o >>= 1) {
        if (tid < o) red[tid] += red[tid + o];
        __syncthreads();
    }
    if (tid == 0) {
        float loss = -(red[0] / (float)N_ITEMS);
        for (int i = BATCHSZ; i < out_size; i++) out[i] = loss;
    }
}

// ---------------- launch ----------------------------------------------------
extern "C" void kernel_launch(void* const* d_in, const int* in_sizes, int n_in,
                              void* d_out, int out_size) {
    const int*   idx    = (const int*)d_in[0];
    const int*   labels = (const int*)d_in[1];
    const float* emb    = (const float*)d_in[2];
    const float* w      = (const float*)d_in[3];
    const float* b      = (const float*)d_in[4];
    float* out = (float*)d_out;

    const int SMEM = 65536 + 16 * 64 * 4 + 2 * 128 * 4;   // 70656 B
    cudaFuncSetAttribute(supcon_kernel, cudaFuncAttributeMaxDynamicSharedMemorySize, SMEM);

    prep_kernel<<<1548, 256>>>(emb, idx, w, b, out);
    classsum_kernel<<<64, 512>>>(labels);
    supcon_kernel<<<GRID_SY, 512, SMEM>>>();
    finalize_kernel<<<1, 1024>>>(labels, out, out_size);
}

// round 10
// speedup vs baseline: 4.2461x; 4.2461x over previous
#include <cuda_runtime.h>
#include <cuda_fp16.h>
#include <cstdint>
#include <math.h>

#define N_ITEMS 8192
#define DIM     64
#define BATCHSZ 4096
#define LN2F    0.69314718055994531f
#define INV_T   14.285714285714286f
#define ITLG2E  20.609947181438156f   /* (1/0.07) * log2(e) */
#define NTILES  2080                  /* 64*65/2 upper-triangle 128x128 tiles */
#define GRID_SY 148

// ---------------- device scratch (no allocations allowed) ----------------
__device__ uint32_t g_fh[N_ITEMS * 32];   // normalized rows, half2-packed [row][32]
__device__ float    g_Z[N_ITEMS];         // exp-sums (atomic accumulated)
__device__ float    g_S[56 * 64];         // per-class feature sums
__device__ int      g_N[56];              // per-class counts
__device__ float    g_partial[64];        // per-CTA loss partials

// ---------------- helpers --------------------------------------------------
static __device__ __forceinline__ uint32_t smem_u32(const void* p) {
    uint32_t a;
    asm("{ .reg .u64 t; cvta.to.shared.u64 t, %1; cvt.u32.u64 %0, t; }" : "=r"(a) : "l"(p));
    return a;
}
static __device__ __forceinline__ float ex2f(float x) {
    float y; asm("ex2.approx.ftz.f32 %0, %1;" : "=f"(y) : "f"(x)); return y;
}
static __device__ __forceinline__ float lg2f(float x) {
    float y; asm("lg2.approx.ftz.f32 %0, %1;" : "=f"(y) : "f"(x)); return y;
}
static __device__ __forceinline__ void cp16(uint32_t dst, const void* src) {
    asm volatile("cp.async.cg.shared.global [%0], [%1], 16;" :: "r"(dst), "l"(src));
}
#define CP_COMMIT() asm volatile("cp.async.commit_group;" ::: "memory")
static __device__ __forceinline__ void ldsm4(uint32_t* r, uint32_t addr) {
    asm volatile("ldmatrix.sync.aligned.m8n8.x4.shared.b16 {%0,%1,%2,%3}, [%4];"
                 : "=r"(r[0]), "=r"(r[1]), "=r"(r[2]), "=r"(r[3]) : "r"(addr));
}
static __device__ __forceinline__ void mma16816(float* d, const uint32_t* a,
                                                uint32_t b0, uint32_t b1) {
    asm volatile("mma.sync.aligned.m16n8k16.row.col.f32.f16.f16.f32 "
                 "{%0,%1,%2,%3}, {%4,%5,%6,%7}, {%8,%9}, {%0,%1,%2,%3};"
                 : "+f"(d[0]), "+f"(d[1]), "+f"(d[2]), "+f"(d[3])
                 : "r"(a[0]), "r"(a[1]), "r"(a[2]), "r"(a[3]), "r"(b0), "r"(b1));
}

// ---------------- kernel 1: normalize + rating + zero scratch --------------
__global__ __launch_bounds__(256) void prep_kernel(const float* __restrict__ emb,
                                                   const int* __restrict__ idx,
                                                   const float* __restrict__ w,
                                                   const float* __restrict__ bias,
                                                   float* __restrict__ out) {
    int bid  = blockIdx.x;
    int wid  = threadIdx.x >> 5;
    int lane = threadIdx.x & 31;
    if (bid < N_ITEMS / 8) {
        int row = bid * 8 + wid;
        float2 v = reinterpret_cast<const float2*>(emb + (size_t)row * DIM)[lane];
        float ss = v.x * v.x + v.y * v.y;
        #pragma unroll
        for (int o = 16; o; o >>= 1) ss += __shfl_xor_sync(0xFFFFFFFFu, ss, o);
        float inv = 1.0f / fmaxf(sqrtf(ss), 1e-12f);
        __half2 h = __floats2half2_rn(v.x * inv, v.y * inv);
        g_fh[row * 32 + lane] = *reinterpret_cast<uint32_t*>(&h);
    } else if (bid < N_ITEMS / 8 + BATCHSZ / 8) {
        int r = (bid - N_ITEMS / 8) * 8 + wid;
        int it = idx[r];
        float2 v  = reinterpret_cast<const float2*>(emb + (size_t)it * DIM)[lane];
        float2 ww = reinterpret_cast<const float2*>(w)[lane];
        float s = v.x * ww.x + v.y * ww.y;
        #pragma unroll
        for (int o = 16; o; o >>= 1) s += __shfl_xor_sync(0xFFFFFFFFu, s, o);
        if (lane == 0) out[r] = 1.0f / (1.0f + __expf(-(s + bias[0])));
    } else {
        int flat = (bid - 1536) * 1024 + threadIdx.x * 4;
        #pragma unroll
        for (int k = 0; k < 4; k++) {
            int f = flat + k;
            if (f < N_ITEMS) g_Z[f] = 0.f;
            else if (f < N_ITEMS + 3584) g_S[f - N_ITEMS] = 0.f;
            else if (f < N_ITEMS + 3584 + 56) g_N[f - N_ITEMS - 3584] = 0;
        }
    }
}

// ---------------- kernel 2: per-class feature sums -------------------------
__global__ __launch_bounds__(512) void classsum_kernel(const int* __restrict__ labels) {
    __shared__ int sl[128];
    int tid = threadIdx.x;
    int d = tid & 63, g = tid >> 6, c0 = g * 7;
    if (tid < 128) sl[tid] = labels[blockIdx.x * 128 + tid];
    __syncthreads();
    float a[7] = {0, 0, 0, 0, 0, 0, 0};
    int   n[7] = {0, 0, 0, 0, 0, 0, 0};
    for (int r = 0; r < 128; r++) {
        int rel = sl[r] - c0;
        if ((unsigned)rel < 7u) {
            uint32_t p = g_fh[(size_t)(blockIdx.x * 128 + r) * 32 + (d >> 1)];
            __half2 h = *reinterpret_cast<__half2*>(&p);
            float v = (d & 1) ? __high2float(h) : __low2float(h);
            #pragma unroll
            for (int q = 0; q < 7; q++) if (rel == q) { a[q] += v; n[q]++; }
        }
    }
    #pragma unroll
    for (int q = 0; q < 7; q++) {
        atomicAdd(&g_S[(c0 + q) * 64 + d], a[q]);
        if (d == 0) atomicAdd(&g_N[c0 + q], n[q]);
    }
}

// ---------------- kernel 3: symmetric Z-only GEMM --------------------------
static __device__ __forceinline__ void decode_tile(int w, int& ti, int& tj) {
    float disc = 16641.0f - 8.0f * (float)w;
    int t = (int)((129.0f - sqrtf(disc)) * 0.5f);
    if (t > 63) t = 63;
    if (t < 0) t = 0;
    while (t > 0 && (t * (129 - t)) / 2 > w) t--;
    while (t < 63 && ((t + 1) * (128 - t)) / 2 <= w) t++;
    ti = t;
    tj = t + (w - (t * (129 - t)) / 2);
}
static __device__ __forceinline__ void load_band(uint32_t sdst, int band, int tid) {
    const char* gsrc = (const char*)g_fh + (size_t)band * 16384;
    #pragma unroll
    for (int i = tid; i < 1024; i += 512) {
        uint32_t off = ((i >> 3) * 128) + ((i & 7) * 16);
        uint32_t sw  = off ^ ((off >> 3) & 0x70);
        cp16(sdst + sw, gsrc + off);
    }
}

__global__ __launch_bounds__(512, 1) void supcon_kernel() {
    extern __shared__ char dyn[];
    float* stage_col = reinterpret_cast<float*>(dyn + 65536);   // [16][64]
    float* stage_row = stage_col + 16 * 64;                     // [2][128]

    const int tid  = threadIdx.x;
    const int w    = tid >> 5;
    const int lane = tid & 31;
    const int wr   = w & 7;
    const int wc   = w >> 3;
    const uint32_t sbase = smem_u32(dyn);
    const int bnoff = (((lane >> 4) & 1) << 3) + (lane & 7);
    const uint32_t bksel = (uint32_t)((lane >> 3) & 1);
    const float negM = -ITLG2E;

    int ti, tj;
    decode_tile(blockIdx.x, ti, tj);
    load_band(sbase, ti, tid);
    load_band(sbase + 16384, tj, tid);
    CP_COMMIT();

    int st = 0;
    for (int wjob = blockIdx.x; wjob < NTILES; wjob += GRID_SY) {
        int tin = ti, tjn = tj;
        int wn = wjob + GRID_SY;
        if (wn < NTILES) decode_tile(wn, tin, tjn);
        uint32_t nstage = sbase + (uint32_t)(st ^ 1) * 32768;
        load_band(nstage, tin, tid);
        load_band(nstage + 16384, tjn, tid);
        CP_COMMIT();
        asm volatile("cp.async.wait_group 1;" ::: "memory");
        __syncthreads();                      // current tile resident

        const uint32_t Ab = sbase + (uint32_t)st * 32768;
        const uint32_t Bb = Ab + 16384;

        uint32_t ah[4][4];
        {
            int arow = wr * 16 + (lane & 15);
            uint32_t rbase = Ab + (uint32_t)arow * 128;
            #pragma unroll
            for (int ks = 0; ks < 4; ks++) {
                uint32_t c = (uint32_t)(ks * 2 + (lane >> 4));
                ldsm4(ah[ks], rbase + ((c ^ (arow & 7)) << 4));
            }
        }

        float rowZ0 = 0.f, rowZ1 = 0.f;
        #pragma unroll
        for (int ntp = 0; ntp < 4; ntp++) {
            float a0[4] = {0.f, 0.f, 0.f, 0.f};
            float a1[4] = {0.f, 0.f, 0.f, 0.f};
            int n = wc * 64 + ntp * 16 + bnoff;
            uint32_t nb = Bb + (uint32_t)n * 128;
            #pragma unroll
            for (int ks = 0; ks < 4; ks++) {
                uint32_t c = (uint32_t)(ks * 2) + bksel;
                uint32_t bb[4];
                ldsm4(bb, nb + ((c ^ (n & 7)) << 4));
                mma16816(a0, ah[ks], bb[0], bb[1]);
                mma16816(a1, ah[ks], bb[2], bb[3]);
            }
            float e00 = ex2f(fmaf(a0[0], ITLG2E, negM));
            float e01 = ex2f(fmaf(a0[1], ITLG2E, negM));
            float e10 = ex2f(fmaf(a0[2], ITLG2E, negM));
            float e11 = ex2f(fmaf(a0[3], ITLG2E, negM));
            float f00 = ex2f(fmaf(a1[0], ITLG2E, negM));
            float f01 = ex2f(fmaf(a1[1], ITLG2E, negM));
            float f10 = ex2f(fmaf(a1[2], ITLG2E, negM));
            float f11 = ex2f(fmaf(a1[3], ITLG2E, negM));
            rowZ0 += (e00 + e01) + (f00 + f01);
            rowZ1 += (e10 + e11) + (f10 + f11);
            float cz0 = e00 + e10, cz1 = e01 + e11;
            float cz2 = f00 + f10, cz3 = f01 + f11;
            #pragma unroll
            for (int off = 4; off <= 16; off <<= 1) {
                cz0 += __shfl_xor_sync(0xFFFFFFFFu, cz0, off);
                cz1 += __shfl_xor_sync(0xFFFFFFFFu, cz1, off);
                cz2 += __shfl_xor_sync(0xFFFFFFFFu, cz2, off);
                cz3 += __shfl_xor_sync(0xFFFFFFFFu, cz3, off);
            }
            if (lane < 4) {
                int cl = ntp * 16 + 2 * lane;
                stage_col[w * 64 + cl]     = cz0;
                stage_col[w * 64 + cl + 1] = cz1;
                stage_col[w * 64 + cl + 8] = cz2;
                stage_col[w * 64 + cl + 9] = cz3;
            }
        }
        #pragma unroll
        for (int off = 1; off <= 2; off <<= 1) {
            rowZ0 += __shfl_xor_sync(0xFFFFFFFFu, rowZ0, off);
            rowZ1 += __shfl_xor_sync(0xFFFFFFFFu, rowZ1, off);
        }
        if ((lane & 3) == 0) {
            int r0 = wr * 16 + (lane >> 2);
            stage_row[wc * 128 + r0]     = rowZ0;
            stage_row[wc * 128 + r0 + 8] = rowZ1;
        }
        __syncthreads();
        if (tid < 128) {
            if (ti != tj) {
                int whalf = (tid >> 6) * 8;
                int cl = tid & 63;
                float v = 0.f;
                #pragma unroll
                for (int k = 0; k < 8; k++) v += stage_col[(whalf + k) * 64 + cl];
                atomicAdd(&g_Z[tj * 128 + tid], v);
            }
        } else if (tid < 256) {
            int r = tid - 128;
            atomicAdd(&g_Z[ti * 128 + r], stage_row[r] + stage_row[128 + r]);
        }
        ti = tin; tj = tjn; st ^= 1;
    }
}

// ---------------- kernel 4: per-row loss, warp-per-row ----------------------
// 64 CTAs x 512 thr (16 warps); warp handles 8 rows -> 64*16*8 = 8192.
__global__ __launch_bounds__(512) void lossrow_kernel(const int* __restrict__ labels) {
    __shared__ float Ss[3584];
    __shared__ float ns[56];
    __shared__ float red[16];
    int tid  = threadIdx.x;
    int w    = tid >> 5;
    int lane = tid & 31;
    for (int i = tid; i < 3584; i += 512) Ss[i] = g_S[i];
    if (tid < 56) ns[tid] = (float)g_N[tid];
    __syncthreads();

    float acc = 0.f;
    #pragma unroll
    for (int k = 0; k < 8; k++) {
        int r = blockIdx.x * 128 + w * 8 + k;
        int lab = labels[r];                              // warp-uniform? no; per-row (same for warp)
        uint32_t p = g_fh[(size_t)r * 32 + lane];         // coalesced 128B per row
        __half2 h = *reinterpret_cast<__half2*>(&p);
        float f0 = __low2float(h), f1 = __high2float(h);
        float sii = f0 * f0 + f1 * f1;
        float di  = f0 * Ss[lab * 64 + 2 * lane] + f1 * Ss[lab * 64 + 2 * lane + 1];
        #pragma unroll
        for (int o = 16; o; o >>= 1) {
            sii += __shfl_xor_sync(0xFFFFFFFFu, sii, o);
            di  += __shfl_xor_sync(0xFFFFFFFFu, di, o);
        }
        if (lane == 0) {
            float Cc  = ns[lab] - 1.0f;
            float eD  = ex2f((sii - 1.0f) * ITLG2E);
            float Zv  = g_Z[r] - eD;
            float Pln = (di - sii - Cc) * INV_T;
            float lnZ = lg2f(Zv + 1e-6f) * LN2F;
            acc += (Pln - Cc * lnZ) / (Cc + 1e-6f);
        }
    }
    if (lane == 0) red[w] = acc;
    __syncthreads();
    if (tid == 0) {
        float s = 0.f;
        #pragma unroll
        for (int i = 0; i < 16; i++) s += red[i];
        g_partial[blockIdx.x] = s;
    }
}

// ---------------- kernel 5: finalize ----------------------------------------
__global__ __launch_bounds__(64) void finalize_kernel(float* __restrict__ out, int out_size) {
    int tid = threadIdx.x;
    float v = g_partial[tid];
    #pragma unroll
    for (int o = 16; o; o >>= 1) v += __shfl_xor_sync(0xFFFFFFFFu, v, o);
    __shared__ float s2[2];
    if ((tid & 31) == 0) s2[tid >> 5] = v;
    __syncthreads();
    if (tid == 0) {
        float loss = -((s2[0] + s2[1]) / (float)N_ITEMS);
        for (int i = BATCHSZ; i < out_size; i++) out[i] = loss;
    }
}

// ---------------- launch ----------------------------------------------------
extern "C" void kernel_launch(void* const* d_in, const int* in_sizes, int n_in,
                              void* d_out, int out_size) {
    const int*   idx    = (const int*)d_in[0];
    const int*   labels = (const int*)d_in[1];
    const float* emb    = (const float*)d_in[2];
    const float* w      = (const float*)d_in[3];
    const float* b      = (const float*)d_in[4];
    float* out = (float*)d_out;

    const int SMEM = 65536 + 16 * 64 * 4 + 2 * 128 * 4;   // 70656 B
    cudaFuncSetAttribute(supcon_kernel, cudaFuncAttributeMaxDynamicSharedMemorySize, SMEM);

    prep_kernel<<<1548, 256>>>(emb, idx, w, b, out);
    classsum_kernel<<<64, 512>>>(labels);
    supcon_kernel<<<GRID_SY, 512, SMEM>>>();
    lossrow_kernel<<<64, 512>>>(labels);
    finalize_kernel<<<1, 64>>>(out, out_size);
}

// round 11
// speedup vs baseline: 4.6026x; 1.0840x over previous
#include <cuda_runtime.h>
#include <cuda_fp16.h>
#include <cstdint>
#include <math.h>

#define N_ITEMS 8192
#define DIM     64
#define BATCHSZ 4096
#define LN2F    0.69314718055994531f
#define INV_T   14.285714285714286f
#define ITLG2E  20.609947181438156f   /* (1/0.07) * log2(e) */
#define NTILES  2080                  /* 64*65/2 upper-triangle 128x128 tiles */
#define GRID_SY 152

// ---------------- device scratch (no allocations allowed) ----------------
__device__ uint32_t g_fh[N_ITEMS * 32];   // normalized rows, half2-packed [row][32]
__device__ float    g_Z[N_ITEMS];         // exp-sums (atomic accumulated)
__device__ float    g_S[56 * 64];         // per-class feature sums
__device__ int      g_N[56];              // per-class counts
__device__ float    g_partial[512];       // per-CTA loss partials

// ---------------- helpers --------------------------------------------------
static __device__ __forceinline__ uint32_t smem_u32(const void* p) {
    uint32_t a;
    asm("{ .reg .u64 t; cvta.to.shared.u64 t, %1; cvt.u32.u64 %0, t; }" : "=r"(a) : "l"(p));
    return a;
}
static __device__ __forceinline__ float ex2f(float x) {
    float y; asm("ex2.approx.ftz.f32 %0, %1;" : "=f"(y) : "f"(x)); return y;
}
static __device__ __forceinline__ float lg2f(float x) {
    float y; asm("lg2.approx.ftz.f32 %0, %1;" : "=f"(y) : "f"(x)); return y;
}
static __device__ __forceinline__ void cp16(uint32_t dst, const void* src) {
    asm volatile("cp.async.cg.shared.global [%0], [%1], 16;" :: "r"(dst), "l"(src));
}
#define CP_COMMIT() asm volatile("cp.async.commit_group;" ::: "memory")
static __device__ __forceinline__ void ldsm4(uint32_t* r, uint32_t addr) {
    asm volatile("ldmatrix.sync.aligned.m8n8.x4.shared.b16 {%0,%1,%2,%3}, [%4];"
                 : "=r"(r[0]), "=r"(r[1]), "=r"(r[2]), "=r"(r[3]) : "r"(addr));
}
static __device__ __forceinline__ void mma16816(float* d, const uint32_t* a,
                                                uint32_t b0, uint32_t b1) {
    asm volatile("mma.sync.aligned.m16n8k16.row.col.f32.f16.f16.f32 "
                 "{%0,%1,%2,%3}, {%4,%5,%6,%7}, {%8,%9}, {%0,%1,%2,%3};"
                 : "+f"(d[0]), "+f"(d[1]), "+f"(d[2]), "+f"(d[3])
                 : "r"(a[0]), "r"(a[1]), "r"(a[2]), "r"(a[3]), "r"(b0), "r"(b1));
}

// ---------------- kernel 1: normalize + rating + zero scratch --------------
__global__ __launch_bounds__(256) void prep_kernel(const float* __restrict__ emb,
                                                   const int* __restrict__ idx,
                                                   const float* __restrict__ w,
                                                   const float* __restrict__ bias,
                                                   float* __restrict__ out) {
    int bid  = blockIdx.x;
    int wid  = threadIdx.x >> 5;
    int lane = threadIdx.x & 31;
    if (bid < N_ITEMS / 8) {
        int row = bid * 8 + wid;
        float2 v = reinterpret_cast<const float2*>(emb + (size_t)row * DIM)[lane];
        float ss = v.x * v.x + v.y * v.y;
        #pragma unroll
        for (int o = 16; o; o >>= 1) ss += __shfl_xor_sync(0xFFFFFFFFu, ss, o);
        float inv = 1.0f / fmaxf(sqrtf(ss), 1e-12f);
        __half2 h = __floats2half2_rn(v.x * inv, v.y * inv);
        g_fh[row * 32 + lane] = *reinterpret_cast<uint32_t*>(&h);
    } else if (bid < N_ITEMS / 8 + BATCHSZ / 8) {
        int r = (bid - N_ITEMS / 8) * 8 + wid;
        int it = idx[r];
        float2 v  = reinterpret_cast<const float2*>(emb + (size_t)it * DIM)[lane];
        float2 ww = reinterpret_cast<const float2*>(w)[lane];
        float s = v.x * ww.x + v.y * ww.y;
        #pragma unroll
        for (int o = 16; o; o >>= 1) s += __shfl_xor_sync(0xFFFFFFFFu, s, o);
        if (lane == 0) out[r] = 1.0f / (1.0f + __expf(-(s + bias[0])));
    } else {
        int flat = (bid - 1536) * 1024 + threadIdx.x * 4;
        #pragma unroll
        for (int k = 0; k < 4; k++) {
            int f = flat + k;
            if (f < N_ITEMS) g_Z[f] = 0.f;
            else if (f < N_ITEMS + 3584) g_S[f - N_ITEMS] = 0.f;
            else if (f < N_ITEMS + 3584 + 56) g_N[f - N_ITEMS - 3584] = 0;
        }
    }
}

// ---------------- kernel 2: per-class feature sums -------------------------
__global__ __launch_bounds__(512) void classsum_kernel(const int* __restrict__ labels) {
    __shared__ int sl[128];
    int tid = threadIdx.x;
    int d = tid & 63, g = tid >> 6, c0 = g * 7;
    if (tid < 128) sl[tid] = labels[blockIdx.x * 128 + tid];
    __syncthreads();
    float a[7] = {0, 0, 0, 0, 0, 0, 0};
    int   n[7] = {0, 0, 0, 0, 0, 0, 0};
    for (int r = 0; r < 128; r++) {
        int rel = sl[r] - c0;
        if ((unsigned)rel < 7u) {
            uint32_t p = g_fh[(size_t)(blockIdx.x * 128 + r) * 32 + (d >> 1)];
            __half2 h = *reinterpret_cast<__half2*>(&p);
            float v = (d & 1) ? __high2float(h) : __low2float(h);
            #pragma unroll
            for (int q = 0; q < 7; q++) if (rel == q) { a[q] += v; n[q]++; }
        }
    }
    #pragma unroll
    for (int q = 0; q < 7; q++) {
        atomicAdd(&g_S[(c0 + q) * 64 + d], a[q]);
        if (d == 0) atomicAdd(&g_N[c0 + q], n[q]);
    }
}

// ---------------- kernel 3: symmetric Z-only GEMM --------------------------
static __device__ __forceinline__ void decode_tile(int w, int& ti, int& tj) {
    float disc = 16641.0f - 8.0f * (float)w;
    int t = (int)((129.0f - sqrtf(disc)) * 0.5f);
    if (t > 63) t = 63;
    if (t < 0) t = 0;
    while (t > 0 && (t * (129 - t)) / 2 > w) t--;
    while (t < 63 && ((t + 1) * (128 - t)) / 2 <= w) t++;
    ti = t;
    tj = t + (w - (t * (129 - t)) / 2);
}
static __device__ __forceinline__ void load_band(uint32_t sdst, int band, int tid) {
    const char* gsrc = (const char*)g_fh + (size_t)band * 16384;
    #pragma unroll
    for (int i = tid; i < 1024; i += 512) {
        uint32_t off = ((i >> 3) * 128) + ((i & 7) * 16);
        uint32_t sw  = off ^ ((off >> 3) & 0x70);
        cp16(sdst + sw, gsrc + off);
    }
}

__global__ __launch_bounds__(512, 1) void supcon_kernel() {
    extern __shared__ char dyn[];
    float* stage_col = reinterpret_cast<float*>(dyn + 65536);   // [16][64]
    float* stage_row = stage_col + 16 * 64;                     // [2][128]

    const int tid  = threadIdx.x;
    const int w    = tid >> 5;
    const int lane = tid & 31;
    const int wr   = w & 7;
    const int wc   = w >> 3;
    const uint32_t sbase = smem_u32(dyn);
    const int bnoff = (((lane >> 4) & 1) << 3) + (lane & 7);
    const uint32_t bksel = (uint32_t)((lane >> 3) & 1);
    const float negM = -ITLG2E;

    int ti, tj;
    decode_tile(blockIdx.x, ti, tj);
    load_band(sbase, ti, tid);
    load_band(sbase + 16384, tj, tid);
    CP_COMMIT();

    int st = 0;
    for (int wjob = blockIdx.x; wjob < NTILES; wjob += GRID_SY) {
        int tin = ti, tjn = tj;
        int wn = wjob + GRID_SY;
        if (wn < NTILES) decode_tile(wn, tin, tjn);
        uint32_t nstage = sbase + (uint32_t)(st ^ 1) * 32768;
        load_band(nstage, tin, tid);
        load_band(nstage + 16384, tjn, tid);
        CP_COMMIT();
        asm volatile("cp.async.wait_group 1;" ::: "memory");
        __syncthreads();                      // current tile resident

        const uint32_t Ab = sbase + (uint32_t)st * 32768;
        const uint32_t Bb = Ab + 16384;

        uint32_t ah[4][4];
        {
            int arow = wr * 16 + (lane & 15);
            uint32_t rbase = Ab + (uint32_t)arow * 128;
            #pragma unroll
            for (int ks = 0; ks < 4; ks++) {
                uint32_t c = (uint32_t)(ks * 2 + (lane >> 4));
                ldsm4(ah[ks], rbase + ((c ^ (arow & 7)) << 4));
            }
        }

        float rowZ0 = 0.f, rowZ1 = 0.f;
        #pragma unroll
        for (int ntp = 0; ntp < 4; ntp++) {
            float a0[4] = {0.f, 0.f, 0.f, 0.f};
            float a1[4] = {0.f, 0.f, 0.f, 0.f};
            int n = wc * 64 + ntp * 16 + bnoff;
            uint32_t nb = Bb + (uint32_t)n * 128;
            #pragma unroll
            for (int ks = 0; ks < 4; ks++) {
                uint32_t c = (uint32_t)(ks * 2) + bksel;
                uint32_t bb[4];
                ldsm4(bb, nb + ((c ^ (n & 7)) << 4));
                mma16816(a0, ah[ks], bb[0], bb[1]);
                mma16816(a1, ah[ks], bb[2], bb[3]);
            }
            float e00 = ex2f(fmaf(a0[0], ITLG2E, negM));
            float e01 = ex2f(fmaf(a0[1], ITLG2E, negM));
            float e10 = ex2f(fmaf(a0[2], ITLG2E, negM));
            float e11 = ex2f(fmaf(a0[3], ITLG2E, negM));
            float f00 = ex2f(fmaf(a1[0], ITLG2E, negM));
            float f01 = ex2f(fmaf(a1[1], ITLG2E, negM));
            float f10 = ex2f(fmaf(a1[2], ITLG2E, negM));
            float f11 = ex2f(fmaf(a1[3], ITLG2E, negM));
            rowZ0 += (e00 + e01) + (f00 + f01);
            rowZ1 += (e10 + e11) + (f10 + f11);
            float cz0 = e00 + e10, cz1 = e01 + e11;
            float cz2 = f00 + f10, cz3 = f01 + f11;
            #pragma unroll
            for (int off = 4; off <= 16; off <<= 1) {
                cz0 += __shfl_xor_sync(0xFFFFFFFFu, cz0, off);
                cz1 += __shfl_xor_sync(0xFFFFFFFFu, cz1, off);
                cz2 += __shfl_xor_sync(0xFFFFFFFFu, cz2, off);
                cz3 += __shfl_xor_sync(0xFFFFFFFFu, cz3, off);
            }
            if (lane < 4) {
                int cl = ntp * 16 + 2 * lane;
                stage_col[w * 64 + cl]     = cz0;
                stage_col[w * 64 + cl + 1] = cz1;
                stage_col[w * 64 + cl + 8] = cz2;
                stage_col[w * 64 + cl + 9] = cz3;
            }
        }
        #pragma unroll
        for (int off = 1; off <= 2; off <<= 1) {
            rowZ0 += __shfl_xor_sync(0xFFFFFFFFu, rowZ0, off);
            rowZ1 += __shfl_xor_sync(0xFFFFFFFFu, rowZ1, off);
        }
        if ((lane & 3) == 0) {
            int r0 = wr * 16 + (lane >> 2);
            stage_row[wc * 128 + r0]     = rowZ0;
            stage_row[wc * 128 + r0 + 8] = rowZ1;
        }
        __syncthreads();
        if (tid < 128) {
            if (ti != tj) {
                int whalf = (tid >> 6) * 8;
                int cl = tid & 63;
                float v = 0.f;
                #pragma unroll
                for (int k = 0; k < 8; k++) v += stage_col[(whalf + k) * 64 + cl];
                atomicAdd(&g_Z[tj * 128 + tid], v);
            }
        } else if (tid < 256) {
            int r = tid - 128;
            atomicAdd(&g_Z[ti * 128 + r], stage_row[r] + stage_row[128 + r]);
        }
        ti = tin; tj = tjn; st ^= 1;
    }
}

// ---------------- kernel 4: per-row loss, warp-per-row ----------------------
// 512 CTAs x 512 thr (16 warps); warp handles exactly 1 row.
__global__ __launch_bounds__(512) void lossrow_kernel(const int* __restrict__ labels) {
    __shared__ float red[16];
    int tid  = threadIdx.x;
    int w    = tid >> 5;
    int lane = tid & 31;
    int r    = blockIdx.x * 16 + w;

    int lab = labels[r];
    uint32_t p = g_fh[(size_t)r * 32 + lane];          // coalesced 128B per row
    __half2 h = *reinterpret_cast<__half2*>(&p);
    float f0 = __low2float(h), f1 = __high2float(h);
    float S0 = g_S[lab * 64 + 2 * lane];
    float S1 = g_S[lab * 64 + 2 * lane + 1];
    float sii = f0 * f0 + f1 * f1;
    float di  = f0 * S0 + f1 * S1;
    #pragma unroll
    for (int o = 16; o; o >>= 1) {
        sii += __shfl_xor_sync(0xFFFFFFFFu, sii, o);
        di  += __shfl_xor_sync(0xFFFFFFFFu, di, o);
    }
    if (lane == 0) {
        float Cc  = (float)g_N[lab] - 1.0f;
        float eD  = ex2f((sii - 1.0f) * ITLG2E);       // diagonal exp term
        float Zv  = g_Z[r] - eD;                       // exclude self
        float Pln = (di - sii - Cc) * INV_T;           // positive-logit sum (ln)
        float lnZ = lg2f(Zv + 1e-6f) * LN2F;
        red[w] = (Pln - Cc * lnZ) / (Cc + 1e-6f);
    }
    __syncthreads();
    if (tid == 0) {
        float s = 0.f;
        #pragma unroll
        for (int i = 0; i < 16; i++) s += red[i];
        g_partial[blockIdx.x] = s;
    }
}

// ---------------- kernel 5: finalize ----------------------------------------
__global__ __launch_bounds__(512) void finalize_kernel(float* __restrict__ out, int out_size) {
    __shared__ float s2[16];
    int tid = threadIdx.x;
    float v = g_partial[tid];
    #pragma unroll
    for (int o = 16; o; o >>= 1) v += __shfl_xor_sync(0xFFFFFFFFu, v, o);
    if ((tid & 31) == 0) s2[tid >> 5] = v;
    __syncthreads();
    if (tid == 0) {
        float s = 0.f;
        #pragma unroll
        for (int i = 0; i < 16; i++) s += s2[i];
        float loss = -(s / (float)N_ITEMS);
        for (int i = BATCHSZ; i < out_size; i++) out[i] = loss;
    }
}

// ---------------- launch ----------------------------------------------------
extern "C" void kernel_launch(void* const* d_in, const int* in_sizes, int n_in,
                              void* d_out, int out_size) {
    const int*   idx    = (const int*)d_in[0];
    const int*   labels = (const int*)d_in[1];
    const float* emb    = (const float*)d_in[2];
    const float* w      = (const float*)d_in[3];
    const float* b      = (const float*)d_in[4];
    float* out = (float*)d_out;

    const int SMEM = 65536 + 16 * 64 * 4 + 2 * 128 * 4;   // 70656 B
    cudaFuncSetAttribute(supcon_kernel, cudaFuncAttributeMaxDynamicSharedMemorySize, SMEM);

    prep_kernel<<<1548, 256>>>(emb, idx, w, b, out);
    classsum_kernel<<<64, 512>>>(labels);
    supcon_kernel<<<GRID_SY, 512, SMEM>>>();
    lossrow_kernel<<<512, 512>>>(labels);
    finalize_kernel<<<1, 512>>>(out, out_size);
}

// round 12
// speedup vs baseline: 4.9771x; 1.0814x over previous
#include <cuda_runtime.h>
#include <cuda_fp16.h>
#include <cstdint>
#include <math.h>

#define N_ITEMS 8192
#define DIM     64
#define BATCHSZ 4096
#define LN2F    0.69314718055994531f
#define INV_T   14.285714285714286f
#define ITLG2E  20.609947181438156f   /* (1/0.07) * log2(e) */
#define NTILES  2080                  /* 64*65/2 upper-triangle 128x128 tiles */
#define GRID_SY 304                   /* 2 CTAs/SM x 152 SMs */

// ---------------- device scratch (no allocations allowed) ----------------
__device__ uint32_t g_fh[N_ITEMS * 32];   // normalized rows, half2-packed [row][32]
__device__ float    g_Z[N_ITEMS];         // exp-sums (atomic accumulated)
__device__ float    g_S[56 * 64];         // per-class feature sums
__device__ int      g_N[56];              // per-class counts
__device__ float    g_partial[512];       // per-CTA loss partials

// ---------------- helpers --------------------------------------------------
static __device__ __forceinline__ uint32_t smem_u32(const void* p) {
    uint32_t a;
    asm("{ .reg .u64 t; cvta.to.shared.u64 t, %1; cvt.u32.u64 %0, t; }" : "=r"(a) : "l"(p));
    return a;
}
static __device__ __forceinline__ float ex2f(float x) {
    float y; asm("ex2.approx.ftz.f32 %0, %1;" : "=f"(y) : "f"(x)); return y;
}
static __device__ __forceinline__ float lg2f(float x) {
    float y; asm("lg2.approx.ftz.f32 %0, %1;" : "=f"(y) : "f"(x)); return y;
}
static __device__ __forceinline__ void cp16(uint32_t dst, const void* src) {
    asm volatile("cp.async.cg.shared.global [%0], [%1], 16;" :: "r"(dst), "l"(src));
}
#define CP_COMMIT() asm volatile("cp.async.commit_group;" ::: "memory")
static __device__ __forceinline__ void ldsm4(uint32_t* r, uint32_t addr) {
    asm volatile("ldmatrix.sync.aligned.m8n8.x4.shared.b16 {%0,%1,%2,%3}, [%4];"
                 : "=r"(r[0]), "=r"(r[1]), "=r"(r[2]), "=r"(r[3]) : "r"(addr));
}
static __device__ __forceinline__ void mma16816(float* d, const uint32_t* a,
                                                uint32_t b0, uint32_t b1) {
    asm volatile("mma.sync.aligned.m16n8k16.row.col.f32.f16.f16.f32 "
                 "{%0,%1,%2,%3}, {%4,%5,%6,%7}, {%8,%9}, {%0,%1,%2,%3};"
                 : "+f"(d[0]), "+f"(d[1]), "+f"(d[2]), "+f"(d[3])
                 : "r"(a[0]), "r"(a[1]), "r"(a[2]), "r"(a[3]), "r"(b0), "r"(b1));
}

// ---------------- kernel 1: normalize + rating + zero scratch --------------
__global__ __launch_bounds__(256) void prep_kernel(const float* __restrict__ emb,
                                                   const int* __restrict__ idx,
                                                   const float* __restrict__ w,
                                                   const float* __restrict__ bias,
                                                   float* __restrict__ out) {
    int bid  = blockIdx.x;
    int wid  = threadIdx.x >> 5;
    int lane = threadIdx.x & 31;
    if (bid < N_ITEMS / 8) {
        int row = bid * 8 + wid;
        float2 v = reinterpret_cast<const float2*>(emb + (size_t)row * DIM)[lane];
        float ss = v.x * v.x + v.y * v.y;
        #pragma unroll
        for (int o = 16; o; o >>= 1) ss += __shfl_xor_sync(0xFFFFFFFFu, ss, o);
        float inv = 1.0f / fmaxf(sqrtf(ss), 1e-12f);
        __half2 h = __floats2half2_rn(v.x * inv, v.y * inv);
        g_fh[row * 32 + lane] = *reinterpret_cast<uint32_t*>(&h);
    } else if (bid < N_ITEMS / 8 + BATCHSZ / 8) {
        int r = (bid - N_ITEMS / 8) * 8 + wid;
        int it = idx[r];
        float2 v  = reinterpret_cast<const float2*>(emb + (size_t)it * DIM)[lane];
        float2 ww = reinterpret_cast<const float2*>(w)[lane];
        float s = v.x * ww.x + v.y * ww.y;
        #pragma unroll
        for (int o = 16; o; o >>= 1) s += __shfl_xor_sync(0xFFFFFFFFu, s, o);
        if (lane == 0) out[r] = 1.0f / (1.0f + __expf(-(s + bias[0])));
    } else {
        int flat = (bid - 1536) * 1024 + threadIdx.x * 4;
        #pragma unroll
        for (int k = 0; k < 4; k++) {
            int f = flat + k;
            if (f < N_ITEMS) g_Z[f] = 0.f;
            else if (f < N_ITEMS + 3584) g_S[f - N_ITEMS] = 0.f;
            else if (f < N_ITEMS + 3584 + 56) g_N[f - N_ITEMS - 3584] = 0;
        }
    }
}

// ---------------- kernel 2: per-class feature sums -------------------------
__global__ __launch_bounds__(512) void classsum_kernel(const int* __restrict__ labels) {
    __shared__ int sl[128];
    int tid = threadIdx.x;
    int d = tid & 63, g = tid >> 6, c0 = g * 7;
    if (tid < 128) sl[tid] = labels[blockIdx.x * 128 + tid];
    __syncthreads();
    float a[7] = {0, 0, 0, 0, 0, 0, 0};
    int   n[7] = {0, 0, 0, 0, 0, 0, 0};
    for (int r = 0; r < 128; r++) {
        int rel = sl[r] - c0;
        if ((unsigned)rel < 7u) {
            uint32_t p = g_fh[(size_t)(blockIdx.x * 128 + r) * 32 + (d >> 1)];
            __half2 h = *reinterpret_cast<__half2*>(&p);
            float v = (d & 1) ? __high2float(h) : __low2float(h);
            #pragma unroll
            for (int q = 0; q < 7; q++) if (rel == q) { a[q] += v; n[q]++; }
        }
    }
    #pragma unroll
    for (int q = 0; q < 7; q++) {
        atomicAdd(&g_S[(c0 + q) * 64 + d], a[q]);
        if (d == 0) atomicAdd(&g_N[c0 + q], n[q]);
    }
}

// ---------------- kernel 3: symmetric Z-only GEMM --------------------------
static __device__ __forceinline__ void decode_tile(int w, int& ti, int& tj) {
    float disc = 16641.0f - 8.0f * (float)w;
    int t = (int)((129.0f - sqrtf(disc)) * 0.5f);
    if (t > 63) t = 63;
    if (t < 0) t = 0;
    while (t > 0 && (t * (129 - t)) / 2 > w) t--;
    while (t < 63 && ((t + 1) * (128 - t)) / 2 <= w) t++;
    ti = t;
    tj = t + (w - (t * (129 - t)) / 2);
}
static __device__ __forceinline__ void load_band(uint32_t sdst, int band, int tid) {
    const char* gsrc = (const char*)g_fh + (size_t)band * 16384;
    #pragma unroll
    for (int i = tid; i < 1024; i += 512) {
        uint32_t off = ((i >> 3) * 128) + ((i & 7) * 16);
        uint32_t sw  = off ^ ((off >> 3) & 0x70);
        cp16(sdst + sw, gsrc + off);
    }
}

__global__ __launch_bounds__(512, 2) void supcon_kernel() {
    extern __shared__ char dyn[];
    float* stage_col = reinterpret_cast<float*>(dyn + 65536);   // [16][64]
    float* stage_row = stage_col + 16 * 64;                     // [2][128]

    const int tid  = threadIdx.x;
    const int w    = tid >> 5;
    const int lane = tid & 31;
    const int wr   = w & 7;
    const int wc   = w >> 3;
    const uint32_t sbase = smem_u32(dyn);
    const int bnoff = (((lane >> 4) & 1) << 3) + (lane & 7);
    const uint32_t bksel = (uint32_t)((lane >> 3) & 1);
    const float negM = -ITLG2E;

    int ti, tj;
    decode_tile(blockIdx.x, ti, tj);
    load_band(sbase, ti, tid);
    load_band(sbase + 16384, tj, tid);
    CP_COMMIT();

    int st = 0;
    for (int wjob = blockIdx.x; wjob < NTILES; wjob += GRID_SY) {
        int tin = ti, tjn = tj;
        int wn = wjob + GRID_SY;
        if (wn < NTILES) decode_tile(wn, tin, tjn);
        uint32_t nstage = sbase + (uint32_t)(st ^ 1) * 32768;
        load_band(nstage, tin, tid);
        load_band(nstage + 16384, tjn, tid);
        CP_COMMIT();
        asm volatile("cp.async.wait_group 1;" ::: "memory");
        __syncthreads();                      // current tile resident

        const uint32_t Ab = sbase + (uint32_t)st * 32768;
        const uint32_t Bb = Ab + 16384;

        uint32_t ah[4][4];
        {
            int arow = wr * 16 + (lane & 15);
            uint32_t rbase = Ab + (uint32_t)arow * 128;
            #pragma unroll
            for (int ks = 0; ks < 4; ks++) {
                uint32_t c = (uint32_t)(ks * 2 + (lane >> 4));
                ldsm4(ah[ks], rbase + ((c ^ (arow & 7)) << 4));
            }
        }

        float rowZ0 = 0.f, rowZ1 = 0.f;
        #pragma unroll
        for (int ntp = 0; ntp < 4; ntp++) {
            float a0[4] = {0.f, 0.f, 0.f, 0.f};
            float a1[4] = {0.f, 0.f, 0.f, 0.f};
            int n = wc * 64 + ntp * 16 + bnoff;
            uint32_t nb = Bb + (uint32_t)n * 128;
            #pragma unroll
            for (int ks = 0; ks < 4; ks++) {
                uint32_t c = (uint32_t)(ks * 2) + bksel;
                uint32_t bb[4];
                ldsm4(bb, nb + ((c ^ (n & 7)) << 4));
                mma16816(a0, ah[ks], bb[0], bb[1]);
                mma16816(a1, ah[ks], bb[2], bb[3]);
            }
            float e00 = ex2f(fmaf(a0[0], ITLG2E, negM));
            float e01 = ex2f(fmaf(a0[1], ITLG2E, negM));
            float e10 = ex2f(fmaf(a0[2], ITLG2E, negM));
            float e11 = ex2f(fmaf(a0[3], ITLG2E, negM));
            float f00 = ex2f(fmaf(a1[0], ITLG2E, negM));
            float f01 = ex2f(fmaf(a1[1], ITLG2E, negM));
            float f10 = ex2f(fmaf(a1[2], ITLG2E, negM));
            float f11 = ex2f(fmaf(a1[3], ITLG2E, negM));
            rowZ0 += (e00 + e01) + (f00 + f01);
            rowZ1 += (e10 + e11) + (f10 + f11);
            float cz0 = e00 + e10, cz1 = e01 + e11;
            float cz2 = f00 + f10, cz3 = f01 + f11;
            #pragma unroll
            for (int off = 4; off <= 16; off <<= 1) {
                cz0 += __shfl_xor_sync(0xFFFFFFFFu, cz0, off);
                cz1 += __shfl_xor_sync(0xFFFFFFFFu, cz1, off);
                cz2 += __shfl_xor_sync(0xFFFFFFFFu, cz2, off);
                cz3 += __shfl_xor_sync(0xFFFFFFFFu, cz3, off);
            }
            if (lane < 4) {
                int cl = ntp * 16 + 2 * lane;
                stage_col[w * 64 + cl]     = cz0;
                stage_col[w * 64 + cl + 1] = cz1;
                stage_col[w * 64 + cl + 8] = cz2;
                stage_col[w * 64 + cl + 9] = cz3;
            }
        }
        #pragma unroll
        for (int off = 1; off <= 2; off <<= 1) {
            rowZ0 += __shfl_xor_sync(0xFFFFFFFFu, rowZ0, off);
            rowZ1 += __shfl_xor_sync(0xFFFFFFFFu, rowZ1, off);
        }
        if ((lane & 3) == 0) {
            int r0 = wr * 16 + (lane >> 2);
            stage_row[wc * 128 + r0]     = rowZ0;
            stage_row[wc * 128 + r0 + 8] = rowZ1;
        }
        __syncthreads();
        if (tid < 128) {
            if (ti != tj) {
                int whalf = (tid >> 6) * 8;
                int cl = tid & 63;
                float v = 0.f;
                #pragma unroll
                for (int k = 0; k < 8; k++) v += stage_col[(whalf + k) * 64 + cl];
                atomicAdd(&g_Z[tj * 128 + tid], v);
            }
        } else if (tid < 256) {
            int r = tid - 128;
            atomicAdd(&g_Z[ti * 128 + r], stage_row[r] + stage_row[128 + r]);
        }
        ti = tin; tj = tjn; st ^= 1;
    }
}

// ---------------- kernel 4: per-row loss, warp-per-row ----------------------
// 512 CTAs x 512 thr (16 warps); warp handles exactly 1 row.
__global__ __launch_bounds__(512) void lossrow_kernel(const int* __restrict__ labels) {
    __shared__ float red[16];
    int tid  = threadIdx.x;
    int w    = tid >> 5;
    int lane = tid & 31;
    int r    = blockIdx.x * 16 + w;

    int lab = labels[r];
    uint32_t p = g_fh[(size_t)r * 32 + lane];          // coalesced 128B per row
    __half2 h = *reinterpret_cast<__half2*>(&p);
    float f0 = __low2float(h), f1 = __high2float(h);
    float S0 = g_S[lab * 64 + 2 * lane];
    float S1 = g_S[lab * 64 + 2 * lane + 1];
    float sii = f0 * f0 + f1 * f1;
    float di  = f0 * S0 + f1 * S1;
    #pragma unroll
    for (int o = 16; o; o >>= 1) {
        sii += __shfl_xor_sync(0xFFFFFFFFu, sii, o);
        di  += __shfl_xor_sync(0xFFFFFFFFu, di, o);
    }
    if (lane == 0) {
        float Cc  = (float)g_N[lab] - 1.0f;
        float eD  = ex2f((sii - 1.0f) * ITLG2E);       // diagonal exp term
        float Zv  = g_Z[r] - eD;                       // exclude self
        float Pln = (di - sii - Cc) * INV_T;           // positive-logit sum (ln)
        float lnZ = lg2f(Zv + 1e-6f) * LN2F;
        red[w] = (Pln - Cc * lnZ) / (Cc + 1e-6f);
    }
    __syncthreads();
    if (tid == 0) {
        float s = 0.f;
        #pragma unroll
        for (int i = 0; i < 16; i++) s += red[i];
        g_partial[blockIdx.x] = s;
    }
}

// ---------------- kernel 5: finalize ----------------------------------------
__global__ __launch_bounds__(512) void finalize_kernel(float* __restrict__ out, int out_size) {
    __shared__ float s2[16];
    int tid = threadIdx.x;
    float v = g_partial[tid];
    #pragma unroll
    for (int o = 16; o; o >>= 1) v += __shfl_xor_sync(0xFFFFFFFFu, v, o);
    if ((tid & 31) == 0) s2[tid >> 5] = v;
    __syncthreads();
    if (tid == 0) {
        float s = 0.f;
        #pragma unroll
        for (int i = 0; i < 16; i++) s += s2[i];
        float loss = -(s / (float)N_ITEMS);
        for (int i = BATCHSZ; i < out_size; i++) out[i] = loss;
    }
}

// ---------------- launch ----------------------------------------------------
extern "C" void kernel_launch(void* const* d_in, const int* in_sizes, int n_in,
                              void* d_out, int out_size) {
    const int*   idx    = (const int*)d_in[0];
    const int*   labels = (const int*)d_in[1];
    const float* emb    = (const float*)d_in[2];
    const float* w      = (const float*)d_in[3];
    const float* b      = (const float*)d_in[4];
    float* out = (float*)d_out;

    const int SMEM = 65536 + 16 * 64 * 4 + 2 * 128 * 4;   // 70656 B
    cudaFuncSetAttribute(supcon_kernel, cudaFuncAttributeMaxDynamicSharedMemorySize, SMEM);

    prep_kernel<<<1548, 256>>>(emb, idx, w, b, out);
    classsum_kernel<<<64, 512>>>(labels);
    supcon_kernel<<<GRID_SY, 512, SMEM>>>();
    lossrow_kernel<<<512, 512>>>(labels);
    finalize_kernel<<<1, 512>>>(out, out_size);
}

// round 13
// speedup vs baseline: 5.1719x; 1.0391x over previous
#include <cuda_runtime.h>
#include <cuda_fp16.h>
#include <cstdint>
#include <math.h>

#define N_ITEMS 8192
#define DIM     64
#define BATCHSZ 4096
#define LN2F    0.69314718055994531f
#define INV_T   14.285714285714286f
#define ITLG2E  20.609947181438156f   /* (1/0.07) * log2(e) */
#define NTILES  2080                  /* 64*65/2 upper-triangle 128x128 tiles */
#define GRID_SY 304                   /* 2 CTAs/SM x 152 SMs */

// ---------------- device scratch (no allocations allowed) ----------------
__device__ uint32_t g_fh[N_ITEMS * 32];   // normalized rows, half2-packed [row][32]
__device__ float    g_Z[N_ITEMS];         // exp-sums (atomic accumulated)
__device__ float    g_S[56 * 64];         // per-class feature sums
__device__ int      g_N[56];              // per-class counts
__device__ float    g_partial[512];       // per-CTA loss partials

// ---------------- helpers --------------------------------------------------
static __device__ __forceinline__ uint32_t smem_u32(const void* p) {
    uint32_t a;
    asm("{ .reg .u64 t; cvta.to.shared.u64 t, %1; cvt.u32.u64 %0, t; }" : "=r"(a) : "l"(p));
    return a;
}
static __device__ __forceinline__ float ex2f(float x) {
    float y; asm("ex2.approx.ftz.f32 %0, %1;" : "=f"(y) : "f"(x)); return y;
}
static __device__ __forceinline__ float lg2f(float x) {
    float y; asm("lg2.approx.ftz.f32 %0, %1;" : "=f"(y) : "f"(x)); return y;
}
static __device__ __forceinline__ void cp16(uint32_t dst, const void* src) {
    asm volatile("cp.async.cg.shared.global [%0], [%1], 16;" :: "r"(dst), "l"(src));
}
#define CP_COMMIT() asm volatile("cp.async.commit_group;" ::: "memory")
static __device__ __forceinline__ void ldsm4(uint32_t* r, uint32_t addr) {
    asm volatile("ldmatrix.sync.aligned.m8n8.x4.shared.b16 {%0,%1,%2,%3}, [%4];"
                 : "=r"(r[0]), "=r"(r[1]), "=r"(r[2]), "=r"(r[3]) : "r"(addr));
}
static __device__ __forceinline__ void mma16816(float* d, const uint32_t* a,
                                                uint32_t b0, uint32_t b1) {
    asm volatile("mma.sync.aligned.m16n8k16.row.col.f32.f16.f16.f32 "
                 "{%0,%1,%2,%3}, {%4,%5,%6,%7}, {%8,%9}, {%0,%1,%2,%3};"
                 : "+f"(d[0]), "+f"(d[1]), "+f"(d[2]), "+f"(d[3])
                 : "r"(a[0]), "r"(a[1]), "r"(a[2]), "r"(a[3]), "r"(b0), "r"(b1));
}

// ---------------- kernel 1: normalize + rating + zero scratch --------------
// half-warp (16 lanes) per row: blocks 0..511 normalize (16 rows/CTA),
// 512..767 rating, 768..779 zero scratch. 780 CTAs -> single wave.
__global__ __launch_bounds__(256) void prep_kernel(const float* __restrict__ emb,
                                                   const int* __restrict__ idx,
                                                   const float* __restrict__ w,
                                                   const float* __restrict__ bias,
                                                   float* __restrict__ out) {
    int bid = blockIdx.x;
    int hw  = threadIdx.x >> 4;      // half-warp in block (0..15)
    int hl  = threadIdx.x & 15;      // lane in half-warp
    if (bid < 512) {
        int row = bid * 16 + hw;
        float4 v = reinterpret_cast<const float4*>(emb + (size_t)row * DIM)[hl];
        float ss = v.x * v.x + v.y * v.y + v.z * v.z + v.w * v.w;
        #pragma unroll
        for (int o = 8; o; o >>= 1) ss += __shfl_xor_sync(0xFFFFFFFFu, ss, o);
        float inv = 1.0f / fmaxf(sqrtf(ss), 1e-12f);
        __half2 h0 = __floats2half2_rn(v.x * inv, v.y * inv);
        __half2 h1 = __floats2half2_rn(v.z * inv, v.w * inv);
        uint2 u;
        u.x = *reinterpret_cast<uint32_t*>(&h0);
        u.y = *reinterpret_cast<uint32_t*>(&h1);
        reinterpret_cast<uint2*>(g_fh + (size_t)row * 32)[hl] = u;
    } else if (bid < 768) {
        int r = (bid - 512) * 16 + hw;
        int it = idx[r];
        float4 v  = reinterpret_cast<const float4*>(emb + (size_t)it * DIM)[hl];
        float4 ww = reinterpret_cast<const float4*>(w)[hl];
        float s = v.x * ww.x + v.y * ww.y + v.z * ww.z + v.w * ww.w;
        #pragma unroll
        for (int o = 8; o; o >>= 1) s += __shfl_xor_sync(0xFFFFFFFFu, s, o);
        if (hl == 0) out[r] = 1.0f / (1.0f + __expf(-(s + bias[0])));
    } else {
        int flat = (bid - 768) * 1024 + threadIdx.x * 4;
        #pragma unroll
        for (int k = 0; k < 4; k++) {
            int f = flat + k;
            if (f < N_ITEMS) g_Z[f] = 0.f;
            else if (f < N_ITEMS + 3584) g_S[f - N_ITEMS] = 0.f;
            else if (f < N_ITEMS + 3584 + 56) g_N[f - N_ITEMS - 3584] = 0;
        }
    }
}

// ---------------- kernel 2: per-class feature sums -------------------------
__global__ __launch_bounds__(512) void classsum_kernel(const int* __restrict__ labels) {
    __shared__ int sl[128];
    int tid = threadIdx.x;
    int d = tid & 63, g = tid >> 6, c0 = g * 7;
    if (tid < 128) sl[tid] = labels[blockIdx.x * 128 + tid];
    __syncthreads();
    float a[7] = {0, 0, 0, 0, 0, 0, 0};
    int   n[7] = {0, 0, 0, 0, 0, 0, 0};
    for (int r = 0; r < 128; r++) {
        int rel = sl[r] - c0;
        if ((unsigned)rel < 7u) {
            uint32_t p = g_fh[(size_t)(blockIdx.x * 128 + r) * 32 + (d >> 1)];
            __half2 h = *reinterpret_cast<__half2*>(&p);
            float v = (d & 1) ? __high2float(h) : __low2float(h);
            #pragma unroll
            for (int q = 0; q < 7; q++) if (rel == q) { a[q] += v; n[q]++; }
        }
    }
    #pragma unroll
    for (int q = 0; q < 7; q++) {
        atomicAdd(&g_S[(c0 + q) * 64 + d], a[q]);
        if (d == 0) atomicAdd(&g_N[c0 + q], n[q]);
    }
}

// ---------------- kernel 3: symmetric Z-only GEMM, chunked + A reuse -------
// Each CTA owns a contiguous chunk of ~7 triangle tiles; consecutive tiles
// usually share the A (row) band -> A loads & fragments reused. Diagonal
// tiles alias B to the A buffer (no B load).
// smem: A ring 2x16K @0, B ring 2x16K @32K, stage_col [16][64] @64K, stage_row [2][128].
static __device__ __forceinline__ void decode_tile(int w, int& ti, int& tj) {
    float disc = 16641.0f - 8.0f * (float)w;
    int t = (int)((129.0f - sqrtf(disc)) * 0.5f);
    if (t > 63) t = 63;
    if (t < 0) t = 0;
    while (t > 0 && (t * (129 - t)) / 2 > w) t--;
    while (t < 63 && ((t + 1) * (128 - t)) / 2 <= w) t++;
    ti = t;
    tj = t + (w - (t * (129 - t)) / 2);
}
static __device__ __forceinline__ void load_band(uint32_t sdst, int band, int tid) {
    const char* gsrc = (const char*)g_fh + (size_t)band * 16384;
    #pragma unroll
    for (int i = tid; i < 1024; i += 512) {
        uint32_t off = ((i >> 3) * 128) + ((i & 7) * 16);
        uint32_t sw  = off ^ ((off >> 3) & 0x70);
        cp16(sdst + sw, gsrc + off);
    }
}

__global__ __launch_bounds__(512, 2) void supcon_kernel() {
    extern __shared__ char dyn[];
    float* stage_col = reinterpret_cast<float*>(dyn + 65536);   // [16][64]
    float* stage_row = stage_col + 16 * 64;                     // [2][128]

    const int tid  = threadIdx.x;
    const int w    = tid >> 5;
    const int lane = tid & 31;
    const int wr   = w & 7;
    const int wc   = w >> 3;
    const uint32_t sbase = smem_u32(dyn);
    const int bnoff = (((lane >> 4) & 1) << 3) + (lane & 7);
    const uint32_t bksel = (uint32_t)((lane >> 3) & 1);
    const float negM = -ITLG2E;

    const int start = (int)(((long long)blockIdx.x * NTILES) / GRID_SY);
    const int end   = (int)(((long long)(blockIdx.x + 1) * NTILES) / GRID_SY);

    int ti, tj;
    decode_tile(start, ti, tj);
    int aslot = 0, bslot = 0;
    bool bIsA = (ti == tj);
    load_band(sbase, ti, tid);
    if (!bIsA) load_band(sbase + 32768, tj, tid);
    CP_COMMIT();

    bool aNew = true;
    uint32_t ah[4][4];

    for (int job = start; job < end; job++) {
        // prefetch next job's bands (A only if row band changes; B unless diagonal)
        bool loadA = false, loadB = false, nbIsA = bIsA;
        int tin = ti, tjn = tj;
        if (job + 1 < end) {
            decode_tile(job + 1, tin, tjn);
            nbIsA = (tin == tjn);
            loadA = (tin != ti);
            loadB = !nbIsA;
            if (loadA) load_band(sbase + (uint32_t)(aslot ^ 1) * 16384, tin, tid);
            if (loadB) load_band(sbase + 32768 + (uint32_t)(bslot ^ 1) * 16384, tjn, tid);
        }
        CP_COMMIT();
        asm volatile("cp.async.wait_group 1;" ::: "memory");
        __syncthreads();                      // current tile resident

        const uint32_t Ab = sbase + (uint32_t)aslot * 16384;
        const uint32_t Bb = bIsA ? Ab : (sbase + 32768 + (uint32_t)bslot * 16384);

        if (aNew) {
            int arow = wr * 16 + (lane & 15);
            uint32_t rbase = Ab + (uint32_t)arow * 128;
            #pragma unroll
            for (int ks = 0; ks < 4; ks++) {
                uint32_t c = (uint32_t)(ks * 2 + (lane >> 4));
                ldsm4(ah[ks], rbase + ((c ^ (arow & 7)) << 4));
            }
        }

        float rowZ0 = 0.f, rowZ1 = 0.f;
        #pragma unroll
        for (int ntp = 0; ntp < 4; ntp++) {
            float a0[4] = {0.f, 0.f, 0.f, 0.f};
            float a1[4] = {0.f, 0.f, 0.f, 0.f};
            int n = wc * 64 + ntp * 16 + bnoff;
            uint32_t nb = Bb + (uint32_t)n * 128;
            #pragma unroll
            for (int ks = 0; ks < 4; ks++) {
                uint32_t c = (uint32_t)(ks * 2) + bksel;
                uint32_t bb[4];
                ldsm4(bb, nb + ((c ^ (n & 7)) << 4));
                mma16816(a0, ah[ks], bb[0], bb[1]);
                mma16816(a1, ah[ks], bb[2], bb[3]);
            }
            float e00 = ex2f(fmaf(a0[0], ITLG2E, negM));
            float e01 = ex2f(fmaf(a0[1], ITLG2E, negM));
            float e10 = ex2f(fmaf(a0[2], ITLG2E, negM));
            float e11 = ex2f(fmaf(a0[3], ITLG2E, negM));
            float f00 = ex2f(fmaf(a1[0], ITLG2E, negM));
            float f01 = ex2f(fmaf(a1[1], ITLG2E, negM));
            float f10 = ex2f(fmaf(a1[2], ITLG2E, negM));
            float f11 = ex2f(fmaf(a1[3], ITLG2E, negM));
            rowZ0 += (e00 + e01) + (f00 + f01);
            rowZ1 += (e10 + e11) + (f10 + f11);
            float cz0 = e00 + e10, cz1 = e01 + e11;
            float cz2 = f00 + f10, cz3 = f01 + f11;
            #pragma unroll
            for (int off = 4; off <= 16; off <<= 1) {
                cz0 += __shfl_xor_sync(0xFFFFFFFFu, cz0, off);
                cz1 += __shfl_xor_sync(0xFFFFFFFFu, cz1, off);
                cz2 += __shfl_xor_sync(0xFFFFFFFFu, cz2, off);
                cz3 += __shfl_xor_sync(0xFFFFFFFFu, cz3, off);
            }
            if (lane < 4) {
                int cl = ntp * 16 + 2 * lane;
                stage_col[w * 64 + cl]     = cz0;
                stage_col[w * 64 + cl + 1] = cz1;
                stage_col[w * 64 + cl + 8] = cz2;
                stage_col[w * 64 + cl + 9] = cz3;
            }
        }
        #pragma unroll
        for (int off = 1; off <= 2; off <<= 1) {
            rowZ0 += __shfl_xor_sync(0xFFFFFFFFu, rowZ0, off);
            rowZ1 += __shfl_xor_sync(0xFFFFFFFFu, rowZ1, off);
        }
        if ((lane & 3) == 0) {
            int r0 = wr * 16 + (lane >> 2);
            stage_row[wc * 128 + r0]     = rowZ0;
            stage_row[wc * 128 + r0 + 8] = rowZ1;
        }
        __syncthreads();                      // stages complete
        if (tid < 128) {
            if (ti != tj) {
                int whalf = (tid >> 6) * 8;
                int cl = tid & 63;
                float v = 0.f;
                #pragma unroll
                for (int k = 0; k < 8; k++) v += stage_col[(whalf + k) * 64 + cl];
                atomicAdd(&g_Z[tj * 128 + tid], v);
            }
        } else if (tid < 256) {
            int r = tid - 128;
            atomicAdd(&g_Z[ti * 128 + r], stage_row[r] + stage_row[128 + r]);
        }
        // advance ring state
        if (loadA) aslot ^= 1;
        if (loadB) bslot ^= 1;
        aNew = loadA;
        ti = tin; tj = tjn; bIsA = nbIsA;
    }
}

// ---------------- kernel 4: per-row loss, warp-per-row ----------------------
__global__ __launch_bounds__(512) void lossrow_kernel(const int* __restrict__ labels) {
    __shared__ float red[16];
    int tid  = threadIdx.x;
    int w    = tid >> 5;
    int lane = tid & 31;
    int r    = blockIdx.x * 16 + w;

    int lab = labels[r];
    uint32_t p = g_fh[(size_t)r * 32 + lane];          // coalesced 128B per row
    __half2 h = *reinterpret_cast<__half2*>(&p);
    float f0 = __low2float(h), f1 = __high2float(h);
    float S0 = g_S[lab * 64 + 2 * lane];
    float S1 = g_S[lab * 64 + 2 * lane + 1];
    float sii = f0 * f0 + f1 * f1;
    float di  = f0 * S0 + f1 * S1;
    #pragma unroll
    for (int o = 16; o; o >>= 1) {
        sii += __shfl_xor_sync(0xFFFFFFFFu, sii, o);
        di  += __shfl_xor_sync(0xFFFFFFFFu, di, o);
    }
    if (lane == 0) {
        float Cc  = (float)g_N[lab] - 1.0f;
        float eD  = ex2f((sii - 1.0f) * ITLG2E);       // diagonal exp term
        float Zv  = g_Z[r] - eD;                       // exclude self
        float Pln = (di - sii - Cc) * INV_T;           // positive-logit sum (ln)
        float lnZ = lg2f(Zv + 1e-6f) * LN2F;
        red[w] = (Pln - Cc * lnZ) / (Cc + 1e-6f);
    }
    __syncthreads();
    if (tid == 0) {
        float s = 0.f;
        #pragma unroll
        for (int i = 0; i < 16; i++) s += red[i];
        g_partial[blockIdx.x] = s;
    }
}

// ---------------- kernel 5: finalize ----------------------------------------
__global__ __launch_bounds__(512) void finalize_kernel(float* __restrict__ out, int out_size) {
    __shared__ float s2[16];
    int tid = threadIdx.x;
    float v = g_partial[tid];
    #pragma unroll
    for (int o = 16; o; o >>= 1) v += __shfl_xor_sync(0xFFFFFFFFu, v, o);
    if ((tid & 31) == 0) s2[tid >> 5] = v;
    __syncthreads();
    if (tid == 0) {
        float s = 0.f;
        #pragma unroll
        for (int i = 0; i < 16; i++) s += s2[i];
        float loss = -(s / (float)N_ITEMS);
        for (int i = BATCHSZ; i < out_size; i++) out[i] = loss;
    }
}

// ---------------- launch ----------------------------------------------------
extern "C" void kernel_launch(void* const* d_in, const int* in_sizes, int n_in,
                              void* d_out, int out_size) {
    const int*   idx    = (const int*)d_in[0];
    const int*   labels = (const int*)d_in[1];
    const float* emb    = (const float*)d_in[2];
    const float* w      = (const float*)d_in[3];
    const float* b      = (const float*)d_in[4];
    float* out = (float*)d_out;

    const int SMEM = 65536 + 16 * 64 * 4 + 2 * 128 * 4;   // 70656 B
    cudaFuncSetAttribute(supcon_kernel, cudaFuncAttributeMaxDynamicSharedMemorySize, SMEM);

    prep_kernel<<<780, 256>>>(emb, idx, w, b, out);
    classsum_kernel<<<64, 512>>>(labels);
    supcon_kernel<<<GRID_SY, 512, SMEM>>>();
    lossrow_kernel<<<512, 512>>>(labels);
    finalize_kernel<<<1, 512>>>(out, out_size);
}